// round 7
// baseline (speedup 1.0000x reference)
#include <cuda_runtime.h>
#include <cuda_fp16.h>
#include <cuda_bf16.h>

// Problem constants (fixed by the reference)
#define NNZ_MAX 3200000
#define NN      100000   // nodes  (< 2^17)
#define HH      50000    // hyperedges (< 2^16)
#define D4      32       // 128 floats = 32 float4 / 32 half4(uint2) per row
#define LEAKY_SLOPE 0.5f

#define TILE    4096                       // scan tile (1024 thr x 4)
#define NBH     ((HH + TILE - 1) / TILE)   // 13
#define NBN     ((NN + TILE - 1) / TILE)   // 25
#define NB      (NBH + NBN)                // 38

// ---------------------------------------------------------------------------
// Static device scratch (no runtime allocation allowed)
// ---------------------------------------------------------------------------
__device__ __align__(16) int      g_cnt_h[HH];
__device__ __align__(16) int      g_cnt_n[NN];
__device__ __align__(16) int      g_off_h[HH + 1];
__device__ __align__(16) int      g_off_n[NN + 1];
__device__ unsigned long long     g_agg[NB];           // (1<<63)|sum lookback slots
__device__ __align__(16) unsigned short g_rank_h[NNZ_MAX]; // rank of edge within its col
__device__ __align__(16) unsigned short g_rank_n[NNZ_MAX]; // rank of edge within its row
__device__ __align__(16) unsigned g_pack_h[NNZ_MAX];   // (row<<15)|val15, sorted by col
__device__ __align__(16) unsigned g_pack_n[NNZ_MAX];   // (col<<16)|val16, sorted by row
__device__ __align__(16) uint2    g_embs_h[NN * D4];   // embs fp16 [N,128] (25.6MB)
__device__ __align__(16) uint2    g_hyper_h[HH * D4];  // hyper fp16 [H,128] (12.8MB)

// ---------------------------------------------------------------------------
// K1: zero histograms + lookback slots + convert embs fp32 -> fp16 (fused)
// ---------------------------------------------------------------------------
__global__ void prep_kernel(const float4* __restrict__ embs4) {
    int i = blockIdx.x * blockDim.x + threadIdx.x;
    int stride = gridDim.x * blockDim.x;
    const int TOT = NN * D4;  // 3.2M float4
    for (; i < TOT; i += stride) {
        float4 v = embs4[i];
        __half2 a = __floats2half2_rn(v.x, v.y);
        __half2 b = __floats2half2_rn(v.z, v.w);
        uint2 o;
        o.x = *reinterpret_cast<unsigned int*>(&a);
        o.y = *reinterpret_cast<unsigned int*>(&b);
        g_embs_h[i] = o;
        if (i < NN) g_cnt_n[i] = 0;
        if (i < HH) g_cnt_h[i] = 0;
        if (i < NB) g_agg[i] = 0ULL;
    }
}

// ---------------------------------------------------------------------------
// K2: histogram of rows and cols; the atomic's return value IS the edge's
// rank within its segment -> stash it so the scatter needs no atomics.
// ---------------------------------------------------------------------------
__global__ void hist_kernel(const int* __restrict__ rows,
                            const int* __restrict__ cols, int nnz) {
    int i = blockIdx.x * blockDim.x + threadIdx.x;
    if (i >= nnz) return;
    int c = cols[i];
    int r = rows[i];
    g_rank_h[i] = (unsigned short)atomicAdd(&g_cnt_h[c], 1);
    g_rank_n[i] = (unsigned short)atomicAdd(&g_cnt_n[r], 1);
}

// ---------------------------------------------------------------------------
// K3: single-kernel scan with decoupled lookback (38 blocks, all resident).
// ---------------------------------------------------------------------------
__global__ void __launch_bounds__(1024, 1) scan_kernel() {
    __shared__ int wsum[32];
    __shared__ int s_boff;

    int b = blockIdx.x;
    bool is_h = (b < NBH);
    int lb       = is_h ? b : b - NBH;
    int nb_local = is_h ? NBH : NBN;
    int M        = is_h ? HH : NN;
    const int* __restrict__ in  = is_h ? g_cnt_h : g_cnt_n;
    int* __restrict__ out       = is_h ? g_off_h : g_off_n;
    int slot_base               = is_h ? 0 : NBH;

    int t = threadIdx.x, lane = t & 31, w = t >> 5;
    int i0 = lb * TILE + t * 4;

    int x0 = 0, x1 = 0, x2 = 0, x3 = 0;
    if (i0 + 3 < M) {
        int4 v = *reinterpret_cast<const int4*>(in + i0);
        x0 = v.x; x1 = v.y; x2 = v.z; x3 = v.w;
    } else {
        if (i0     < M) x0 = in[i0];
        if (i0 + 1 < M) x1 = in[i0 + 1];
        if (i0 + 2 < M) x2 = in[i0 + 2];
        if (i0 + 3 < M) x3 = in[i0 + 3];
    }
    int tsum = x0 + x1 + x2 + x3;

    int v = tsum;
    #pragma unroll
    for (int d = 1; d < 32; d <<= 1) {
        int y = __shfl_up_sync(0xffffffffu, v, d);
        if (lane >= d) v += y;
    }
    if (lane == 31) wsum[w] = v;
    __syncthreads();
    if (w == 0) {
        int s = wsum[lane];
        #pragma unroll
        for (int d = 1; d < 32; d <<= 1) {
            int y = __shfl_up_sync(0xffffffffu, s, d);
            if (lane >= d) s += y;
        }
        wsum[lane] = s;
    }
    __syncthreads();
    int block_total = wsum[31];

    if (t == 0) {
        unsigned long long packed = (1ULL << 63) | (unsigned long long)(unsigned)block_total;
        atomicExch(&g_agg[slot_base + lb], packed);
    }
    if (w == 0) {
        int psum = 0;
        if (lane < lb) {
            unsigned long long pv;
            do {
                pv = atomicAdd(&g_agg[slot_base + lane], 0ULL);
            } while (!(pv >> 63));
            psum = (int)(unsigned)pv;
        }
        #pragma unroll
        for (int d = 16; d; d >>= 1) psum += __shfl_down_sync(0xffffffffu, psum, d);
        if (lane == 0) s_boff = psum;
    }
    __syncthreads();
    int boff = s_boff;

    int woff = (w > 0) ? wsum[w - 1] : 0;
    int excl = boff + woff + v - tsum;
    int o0 = excl, o1 = o0 + x0, o2 = o1 + x1, o3 = o2 + x2;
    if (i0 + 3 < M) {
        *reinterpret_cast<int4*>(out + i0) = make_int4(o0, o1, o2, o3);
    } else {
        if (i0     < M) out[i0]     = o0;
        if (i0 + 1 < M) out[i0 + 1] = o1;
        if (i0 + 2 < M) out[i0 + 2] = o2;
    }
    if (t == 0 && lb == nb_local - 1) out[M] = boff + block_total;
}

// ---------------------------------------------------------------------------
// K4: atomic-free scatter. pos = off[key] + precomputed rank.
// Pairs packed to 4B: h = (row:17 | val:15), n = (col:16 | val:16).
// ---------------------------------------------------------------------------
__global__ void scatter_kernel(const float* __restrict__ vals,
                               const int* __restrict__ rows,
                               const int* __restrict__ cols, int nnz) {
    int i = blockIdx.x * blockDim.x + threadIdx.x;
    if (i >= nnz) return;
    float v = vals[i];
    int r = rows[i];
    int c = cols[i];

    unsigned vh = __float2uint_rn(v * 32768.f);
    if (vh > 32767u) vh = 32767u;
    unsigned vn = __float2uint_rn(v * 65536.f);
    if (vn > 65535u) vn = 65535u;

    int p = __ldg(&g_off_h[c]) + (int)g_rank_h[i];
    __stcs(&g_pack_h[p], ((unsigned)r << 15) | vh);
    int q = __ldg(&g_off_n[r]) + (int)g_rank_n[i];
    __stcs(&g_pack_n[q], ((unsigned)c << 16) | vn);
}

// ---------------------------------------------------------------------------
// Warp-per-segment reduce: fp16 gather (8B/lane = 256B/row), fp32 accumulate.
// Packed pairs: ONE shfl per edge; decode on each lane (FMA/ALU pipes idle).
// ---------------------------------------------------------------------------
__device__ __forceinline__ void edge_fma(float4& acc, float vv, int rr, int lane,
                                         const uint2* __restrict__ src) {
    uint2 em = __ldg(&src[rr * D4 + lane]);
    __half2 h0 = *reinterpret_cast<__half2*>(&em.x);
    __half2 h1 = *reinterpret_cast<__half2*>(&em.y);
    float2 f0 = __half22float2(h0);
    float2 f1 = __half22float2(h1);
    acc.x = fmaf(vv, f0.x, acc.x);
    acc.y = fmaf(vv, f0.y, acc.y);
    acc.z = fmaf(vv, f1.x, acc.z);
    acc.w = fmaf(vv, f1.y, acc.w);
}

template <int SHIFT>
__device__ __forceinline__ float4 segment_reduce_packed(const int* __restrict__ off,
                                                        const unsigned* __restrict__ pairs,
                                                        const uint2* __restrict__ src,
                                                        int seg, int lane) {
    const unsigned MASK = (1u << SHIFT) - 1u;
    const float SCALE = 1.0f / (float)(1u << SHIFT);
    int s = off[seg];
    int e = off[seg + 1];
    float4 acc = make_float4(0.f, 0.f, 0.f, 0.f);

    int idx = s + lane;
    unsigned pr = (idx < e) ? __ldcs(&pairs[idx]) : 0u;

    for (int base = s; base < e; base += 32) {
        unsigned mine = pr;
        int nidx = base + 32 + lane;                   // prefetch next chunk
        pr = (nidx < e) ? __ldcs(&pairs[nidx]) : 0u;

        int cnt = e - base;
        if (cnt >= 32) {
            #pragma unroll 8
            for (int k = 0; k < 32; k++) {
                unsigned pk = __shfl_sync(0xffffffffu, mine, k);
                int   rr = (int)(pk >> SHIFT);
                float vv = (float)(pk & MASK) * SCALE;
                edge_fma(acc, vv, rr, lane, src);
            }
        } else {
            for (int k = 0; k < cnt; k++) {
                unsigned pk = __shfl_sync(0xffffffffu, mine, k);
                int   rr = (int)(pk >> SHIFT);
                float vv = (float)(pk & MASK) * SCALE;
                edge_fma(acc, vv, rr, lane, src);
            }
        }
    }
    return acc;
}

// K5: hyper = A^T @ embs  (one warp per hyperedge, fp16 out)
__global__ void __launch_bounds__(256) spmm1_kernel() {
    int gw = (blockIdx.x * blockDim.x + threadIdx.x) >> 5;
    if (gw >= HH) return;
    int lane = threadIdx.x & 31;
    float4 acc = segment_reduce_packed<15>(g_off_h, g_pack_h, g_embs_h, gw, lane);
    __half2 a = __floats2half2_rn(acc.x, acc.y);
    __half2 b = __floats2half2_rn(acc.z, acc.w);
    uint2 o;
    o.x = *reinterpret_cast<unsigned int*>(&a);
    o.y = *reinterpret_cast<unsigned int*>(&b);
    g_hyper_h[gw * D4 + lane] = o;
}

// K6: out = LeakyReLU(A @ hyper)  (one warp per node, fp32 out, streamed)
__global__ void __launch_bounds__(256) spmm2_kernel(float4* __restrict__ out4) {
    int gw = (blockIdx.x * blockDim.x + threadIdx.x) >> 5;
    if (gw >= NN) return;
    int lane = threadIdx.x & 31;
    float4 acc = segment_reduce_packed<16>(g_off_n, g_pack_n, g_hyper_h, gw, lane);
    acc.x = acc.x >= 0.f ? acc.x : LEAKY_SLOPE * acc.x;
    acc.y = acc.y >= 0.f ? acc.y : LEAKY_SLOPE * acc.y;
    acc.z = acc.z >= 0.f ? acc.z : LEAKY_SLOPE * acc.z;
    acc.w = acc.w >= 0.f ? acc.w : LEAKY_SLOPE * acc.w;
    __stcs(&out4[gw * D4 + lane], acc);
}

// ---------------------------------------------------------------------------
// Launch
// ---------------------------------------------------------------------------
extern "C" void kernel_launch(void* const* d_in, const int* in_sizes, int n_in,
                              void* d_out, int out_size) {
    const float* vals = (const float*)d_in[0];
    const float* embs = (const float*)d_in[1];
    const int*   rows = (const int*)d_in[2];
    const int*   cols = (const int*)d_in[3];
    int nnz = in_sizes[0];
    if (nnz > NNZ_MAX) nnz = NNZ_MAX;

    float4* out4 = (float4*)d_out;
    const float4* embs4 = (const float4*)embs;

    const int B = 256;
    int nnz_blocks = (nnz + B - 1) / B;

    prep_kernel<<<(NN * D4 + B - 1) / B, B>>>(embs4);     // zero + fp16 convert
    hist_kernel<<<nnz_blocks, B>>>(rows, cols, nnz);      // counts + ranks
    scan_kernel<<<NB, 1024>>>();                          // offsets (lookback)
    scatter_kernel<<<nnz_blocks, B>>>(vals, rows, cols, nnz);  // atomic-free

    spmm1_kernel<<<(HH * 32 + B - 1) / B, B>>>();
    spmm2_kernel<<<(NN * 32 + B - 1) / B, B>>>(out4);
}

// round 8
// speedup vs baseline: 1.0420x; 1.0420x over previous
#include <cuda_runtime.h>
#include <cuda_fp16.h>
#include <cuda_bf16.h>

// Problem constants (fixed by the reference)
#define NNZ_MAX 3200000
#define NN      100000   // nodes  (< 2^17)
#define HH      50000    // hyperedges (< 2^16)
#define D4      32       // 128 floats = 32 half4(uint2) per row
#define LEAKY_SLOPE 0.5f

#define TILE    4096                       // scan tile (1024 thr x 4)
#define NBH     ((HH + TILE - 1) / TILE)   // 13
#define NBN     ((NN + TILE - 1) / TILE)   // 25

// ---------------------------------------------------------------------------
// Static device scratch (no runtime allocation allowed)
// ---------------------------------------------------------------------------
__device__ __align__(16) int      g_cnt_h[HH];
__device__ __align__(16) int      g_cnt_n[NN];
__device__ __align__(16) int      g_off_h[HH + 1];
__device__ __align__(16) int      g_off_n[NN + 1];
__device__ unsigned long long     g_agg_h[NBH];
__device__ unsigned long long     g_agg_n[NBN];
__device__ __align__(16) unsigned short g_rank_h[NNZ_MAX];
__device__ __align__(16) unsigned short g_rank_n[NNZ_MAX];
__device__ __align__(16) unsigned g_pack_h[NNZ_MAX];   // (row<<15)|val15, col-sorted
__device__ __align__(16) unsigned g_pack_n[NNZ_MAX];   // (col<<16)|val16, row-sorted
__device__ __align__(16) uint2    g_embs_h[NN * D4];   // embs fp16 (25.6MB)
__device__ __align__(16) uint2    g_hyper_h[HH * D4];  // hyper fp16 (12.8MB)

// ---------------------------------------------------------------------------
// Chain A head: zero h-side counters + lookback slots
// ---------------------------------------------------------------------------
__global__ void zero_h_kernel() {
    int i = blockIdx.x * blockDim.x + threadIdx.x;
    if (i < HH) g_cnt_h[i] = 0;
    if (i < NBH) g_agg_h[i] = 0ULL;
}

// ---------------------------------------------------------------------------
// Chain B head: zero n-side counters/slots + convert embs fp32 -> fp16
// ---------------------------------------------------------------------------
__global__ void prep_kernel(const float4* __restrict__ embs4) {
    int i = blockIdx.x * blockDim.x + threadIdx.x;
    int stride = gridDim.x * blockDim.x;
    const int TOT = NN * D4;  // 3.2M float4
    for (; i < TOT; i += stride) {
        float4 v = embs4[i];
        __half2 a = __floats2half2_rn(v.x, v.y);
        __half2 b = __floats2half2_rn(v.z, v.w);
        uint2 o;
        o.x = *reinterpret_cast<unsigned int*>(&a);
        o.y = *reinterpret_cast<unsigned int*>(&b);
        g_embs_h[i] = o;
        if (i < NN) g_cnt_n[i] = 0;
        if (i < NBN) g_agg_n[i] = 0ULL;
    }
}

// ---------------------------------------------------------------------------
// Histograms (one side each): 2 edges/thread, rank pair packed into one uint.
// ---------------------------------------------------------------------------
__global__ void hist_h_kernel(const int* __restrict__ cols, int nnz) {
    int i = (blockIdx.x * blockDim.x + threadIdx.x) * 2;
    if (i + 1 < nnz) {
        int2 c = *reinterpret_cast<const int2*>(cols + i);
        unsigned r0 = (unsigned)atomicAdd(&g_cnt_h[c.x], 1);
        unsigned r1 = (unsigned)atomicAdd(&g_cnt_h[c.y], 1);
        *reinterpret_cast<unsigned*>(g_rank_h + i) = r0 | (r1 << 16);
    } else if (i < nnz) {
        g_rank_h[i] = (unsigned short)atomicAdd(&g_cnt_h[cols[i]], 1);
    }
}

__global__ void hist_n_kernel(const int* __restrict__ rows, int nnz) {
    int i = (blockIdx.x * blockDim.x + threadIdx.x) * 2;
    if (i + 1 < nnz) {
        int2 r = *reinterpret_cast<const int2*>(rows + i);
        unsigned r0 = (unsigned)atomicAdd(&g_cnt_n[r.x], 1);
        unsigned r1 = (unsigned)atomicAdd(&g_cnt_n[r.y], 1);
        *reinterpret_cast<unsigned*>(g_rank_n + i) = r0 | (r1 << 16);
    } else if (i < nnz) {
        g_rank_n[i] = (unsigned short)atomicAdd(&g_cnt_n[rows[i]], 1);
    }
}

// ---------------------------------------------------------------------------
// Decoupled-lookback scan (all blocks resident; <=25 blocks per side)
// ---------------------------------------------------------------------------
__device__ __forceinline__ void scan_body(const int* __restrict__ in,
                                          int* __restrict__ out,
                                          unsigned long long* __restrict__ agg,
                                          int M, int nb) {
    __shared__ int wsum[32];
    __shared__ int s_boff;
    int lb = blockIdx.x;
    int t = threadIdx.x, lane = t & 31, w = t >> 5;
    int i0 = lb * TILE + t * 4;

    int x0 = 0, x1 = 0, x2 = 0, x3 = 0;
    if (i0 + 3 < M) {
        int4 v = *reinterpret_cast<const int4*>(in + i0);
        x0 = v.x; x1 = v.y; x2 = v.z; x3 = v.w;
    } else {
        if (i0     < M) x0 = in[i0];
        if (i0 + 1 < M) x1 = in[i0 + 1];
        if (i0 + 2 < M) x2 = in[i0 + 2];
        if (i0 + 3 < M) x3 = in[i0 + 3];
    }
    int tsum = x0 + x1 + x2 + x3;

    int v = tsum;
    #pragma unroll
    for (int d = 1; d < 32; d <<= 1) {
        int y = __shfl_up_sync(0xffffffffu, v, d);
        if (lane >= d) v += y;
    }
    if (lane == 31) wsum[w] = v;
    __syncthreads();
    if (w == 0) {
        int s = wsum[lane];
        #pragma unroll
        for (int d = 1; d < 32; d <<= 1) {
            int y = __shfl_up_sync(0xffffffffu, s, d);
            if (lane >= d) s += y;
        }
        wsum[lane] = s;
    }
    __syncthreads();
    int block_total = wsum[31];

    if (t == 0) {
        unsigned long long packed = (1ULL << 63) | (unsigned long long)(unsigned)block_total;
        atomicExch(&agg[lb], packed);
    }
    if (w == 0) {
        int psum = 0;
        if (lane < lb) {
            unsigned long long pv;
            do { pv = atomicAdd(&agg[lane], 0ULL); } while (!(pv >> 63));
            psum = (int)(unsigned)pv;
        }
        #pragma unroll
        for (int d = 16; d; d >>= 1) psum += __shfl_down_sync(0xffffffffu, psum, d);
        if (lane == 0) s_boff = psum;
    }
    __syncthreads();
    int boff = s_boff;

    int woff = (w > 0) ? wsum[w - 1] : 0;
    int excl = boff + woff + v - tsum;
    int o0 = excl, o1 = o0 + x0, o2 = o1 + x1, o3 = o2 + x2;
    if (i0 + 3 < M) {
        *reinterpret_cast<int4*>(out + i0) = make_int4(o0, o1, o2, o3);
    } else {
        if (i0     < M) out[i0]     = o0;
        if (i0 + 1 < M) out[i0 + 1] = o1;
        if (i0 + 2 < M) out[i0 + 2] = o2;
    }
    if (t == 0 && lb == nb - 1) out[M] = boff + block_total;
}

__global__ void __launch_bounds__(1024, 1) scan_h_kernel() {
    scan_body(g_cnt_h, g_off_h, g_agg_h, HH, NBH);
}
__global__ void __launch_bounds__(1024, 1) scan_n_kernel() {
    scan_body(g_cnt_n, g_off_n, g_agg_n, NN, NBN);
}

// ---------------------------------------------------------------------------
// Atomic-free scatters (one side each), 2 edges/thread.
// ---------------------------------------------------------------------------
__global__ void scatter_h_kernel(const float* __restrict__ vals,
                                 const int* __restrict__ rows,
                                 const int* __restrict__ cols, int nnz) {
    int i = (blockIdx.x * blockDim.x + threadIdx.x) * 2;
    if (i + 1 < nnz) {
        float2 v = *reinterpret_cast<const float2*>(vals + i);
        int2 r = *reinterpret_cast<const int2*>(rows + i);
        int2 c = *reinterpret_cast<const int2*>(cols + i);
        unsigned rk = *reinterpret_cast<const unsigned*>(g_rank_h + i);
        unsigned v0 = __float2uint_rn(v.x * 32768.f); if (v0 > 32767u) v0 = 32767u;
        unsigned v1 = __float2uint_rn(v.y * 32768.f); if (v1 > 32767u) v1 = 32767u;
        int p0 = __ldg(&g_off_h[c.x]) + (int)(rk & 0xffffu);
        int p1 = __ldg(&g_off_h[c.y]) + (int)(rk >> 16);
        __stcs(&g_pack_h[p0], ((unsigned)r.x << 15) | v0);
        __stcs(&g_pack_h[p1], ((unsigned)r.y << 15) | v1);
    } else if (i < nnz) {
        unsigned v0 = __float2uint_rn(vals[i] * 32768.f); if (v0 > 32767u) v0 = 32767u;
        int p0 = __ldg(&g_off_h[cols[i]]) + (int)g_rank_h[i];
        __stcs(&g_pack_h[p0], ((unsigned)rows[i] << 15) | v0);
    }
}

__global__ void scatter_n_kernel(const float* __restrict__ vals,
                                 const int* __restrict__ rows,
                                 const int* __restrict__ cols, int nnz) {
    int i = (blockIdx.x * blockDim.x + threadIdx.x) * 2;
    if (i + 1 < nnz) {
        float2 v = *reinterpret_cast<const float2*>(vals + i);
        int2 r = *reinterpret_cast<const int2*>(rows + i);
        int2 c = *reinterpret_cast<const int2*>(cols + i);
        unsigned rk = *reinterpret_cast<const unsigned*>(g_rank_n + i);
        unsigned v0 = __float2uint_rn(v.x * 65536.f); if (v0 > 65535u) v0 = 65535u;
        unsigned v1 = __float2uint_rn(v.y * 65536.f); if (v1 > 65535u) v1 = 65535u;
        int q0 = __ldg(&g_off_n[r.x]) + (int)(rk & 0xffffu);
        int q1 = __ldg(&g_off_n[r.y]) + (int)(rk >> 16);
        __stcs(&g_pack_n[q0], ((unsigned)c.x << 16) | v0);
        __stcs(&g_pack_n[q1], ((unsigned)c.y << 16) | v1);
    } else if (i < nnz) {
        unsigned v0 = __float2uint_rn(vals[i] * 65536.f); if (v0 > 65535u) v0 = 65535u;
        int q0 = __ldg(&g_off_n[rows[i]]) + (int)g_rank_n[i];
        __stcs(&g_pack_n[q0], ((unsigned)cols[i] << 16) | v0);
    }
}

// ---------------------------------------------------------------------------
// Warp-per-segment reduce: fp16 gather, fp32 accumulate, one shfl per edge.
// ---------------------------------------------------------------------------
__device__ __forceinline__ void edge_fma(float4& acc, float vv, int rr, int lane,
                                         const uint2* __restrict__ src) {
    uint2 em = __ldg(&src[rr * D4 + lane]);
    __half2 h0 = *reinterpret_cast<__half2*>(&em.x);
    __half2 h1 = *reinterpret_cast<__half2*>(&em.y);
    float2 f0 = __half22float2(h0);
    float2 f1 = __half22float2(h1);
    acc.x = fmaf(vv, f0.x, acc.x);
    acc.y = fmaf(vv, f0.y, acc.y);
    acc.z = fmaf(vv, f1.x, acc.z);
    acc.w = fmaf(vv, f1.y, acc.w);
}

template <int SHIFT>
__device__ __forceinline__ float4 segment_reduce_packed(const int* __restrict__ off,
                                                        const unsigned* __restrict__ pairs,
                                                        const uint2* __restrict__ src,
                                                        int seg, int lane) {
    const unsigned MASK = (1u << SHIFT) - 1u;
    const float SCALE = 1.0f / (float)(1u << SHIFT);
    int s = off[seg];
    int e = off[seg + 1];
    float4 acc = make_float4(0.f, 0.f, 0.f, 0.f);

    int idx = s + lane;
    unsigned pr = (idx < e) ? __ldcs(&pairs[idx]) : 0u;

    for (int base = s; base < e; base += 32) {
        unsigned mine = pr;
        int nidx = base + 32 + lane;                   // prefetch next chunk
        pr = (nidx < e) ? __ldcs(&pairs[nidx]) : 0u;

        int cnt = e - base;
        if (cnt >= 32) {
            #pragma unroll 8
            for (int k = 0; k < 32; k++) {
                unsigned pk = __shfl_sync(0xffffffffu, mine, k);
                int   rr = (int)(pk >> SHIFT);
                float vv = (float)(pk & MASK) * SCALE;
                edge_fma(acc, vv, rr, lane, src);
            }
        } else {
            for (int k = 0; k < cnt; k++) {
                unsigned pk = __shfl_sync(0xffffffffu, mine, k);
                int   rr = (int)(pk >> SHIFT);
                float vv = (float)(pk & MASK) * SCALE;
                edge_fma(acc, vv, rr, lane, src);
            }
        }
    }
    return acc;
}

// spmm1: hyper = A^T @ embs  (one warp per hyperedge, fp16 out)
__global__ void __launch_bounds__(256) spmm1_kernel() {
    int gw = (blockIdx.x * blockDim.x + threadIdx.x) >> 5;
    if (gw >= HH) return;
    int lane = threadIdx.x & 31;
    float4 acc = segment_reduce_packed<15>(g_off_h, g_pack_h, g_embs_h, gw, lane);
    __half2 a = __floats2half2_rn(acc.x, acc.y);
    __half2 b = __floats2half2_rn(acc.z, acc.w);
    uint2 o;
    o.x = *reinterpret_cast<unsigned int*>(&a);
    o.y = *reinterpret_cast<unsigned int*>(&b);
    g_hyper_h[gw * D4 + lane] = o;
}

// spmm2: out = LeakyReLU(A @ hyper)  (one warp per node, fp32 out)
__global__ void __launch_bounds__(256) spmm2_kernel(float4* __restrict__ out4) {
    int gw = (blockIdx.x * blockDim.x + threadIdx.x) >> 5;
    if (gw >= NN) return;
    int lane = threadIdx.x & 31;
    float4 acc = segment_reduce_packed<16>(g_off_n, g_pack_n, g_hyper_h, gw, lane);
    acc.x = acc.x >= 0.f ? acc.x : LEAKY_SLOPE * acc.x;
    acc.y = acc.y >= 0.f ? acc.y : LEAKY_SLOPE * acc.y;
    acc.z = acc.z >= 0.f ? acc.z : LEAKY_SLOPE * acc.z;
    acc.w = acc.w >= 0.f ? acc.w : LEAKY_SLOPE * acc.w;
    __stcs(&out4[gw * D4 + lane], acc);
}

// ---------------------------------------------------------------------------
// Launch: fork-join dual chains so the n-side sort hides under the h-side
// sort + spmm1. Stream/event creation is host-side only (no device alloc);
// forked stream fully joins the origin stream before return.
// ---------------------------------------------------------------------------
extern "C" void kernel_launch(void* const* d_in, const int* in_sizes, int n_in,
                              void* d_out, int out_size) {
    const float* vals = (const float*)d_in[0];
    const float* embs = (const float*)d_in[1];
    const int*   rows = (const int*)d_in[2];
    const int*   cols = (const int*)d_in[3];
    int nnz = in_sizes[0];
    if (nnz > NNZ_MAX) nnz = NNZ_MAX;

    float4* out4 = (float4*)d_out;
    const float4* embs4 = (const float4*)embs;

    const int B = 256;
    int half_blocks = ((nnz + 1) / 2 + B - 1) / B;

    cudaStream_t s1;
    cudaStreamCreateWithFlags(&s1, cudaStreamNonBlocking);
    cudaEvent_t evFork, evPrep, evScatN;
    cudaEventCreateWithFlags(&evFork,  cudaEventDisableTiming);
    cudaEventCreateWithFlags(&evPrep,  cudaEventDisableTiming);
    cudaEventCreateWithFlags(&evScatN, cudaEventDisableTiming);

    // fork
    cudaEventRecord(evFork, 0);
    cudaStreamWaitEvent(s1, evFork, 0);

    // chain B (stream s1): prep -> hist_n -> scan_n -> scatter_n
    prep_kernel<<<(NN * D4 + B - 1) / B, B, 0, s1>>>(embs4);
    cudaEventRecord(evPrep, s1);
    hist_n_kernel<<<half_blocks, B, 0, s1>>>(rows, nnz);
    scan_n_kernel<<<NBN, 1024, 0, s1>>>();
    scatter_n_kernel<<<half_blocks, B, 0, s1>>>(vals, rows, cols, nnz);
    cudaEventRecord(evScatN, s1);

    // chain A (origin stream): zero_h -> hist_h -> scan_h -> scatter_h
    zero_h_kernel<<<(HH + B - 1) / B, B>>>();
    hist_h_kernel<<<half_blocks, B>>>(cols, nnz);
    scan_h_kernel<<<NBH, 1024>>>();
    scatter_h_kernel<<<half_blocks, B>>>(vals, rows, cols, nnz);

    // spmm1 needs embs_h (chain B's prep) + chain A's pack_h
    cudaStreamWaitEvent(0, evPrep, 0);
    spmm1_kernel<<<(HH * 32 + B - 1) / B, B>>>();

    // spmm2 needs pack_n (chain B fully joined) + hyper (spmm1)
    cudaStreamWaitEvent(0, evScatN, 0);
    spmm2_kernel<<<(NN * 32 + B - 1) / B, B>>>(out4);
}

// round 9
// speedup vs baseline: 1.1012x; 1.0568x over previous
#include <cuda_runtime.h>
#include <cuda_fp16.h>
#include <cuda_bf16.h>

// Problem constants (fixed by the reference)
#define NNZ_MAX 3200000
#define NN      100000   // nodes  (< 2^17)
#define HH      50000    // hyperedges (< 2^16)
#define D4      32       // 128 floats per row
#define LEAKY_SLOPE 0.5f

#define TILE    4096                       // scan tile (1024 thr x 4)
#define NBH     ((HH + TILE - 1) / TILE)   // 13
#define NBN     ((NN + TILE - 1) / TILE)   // 25

// ---------------------------------------------------------------------------
// Static device scratch (no runtime allocation allowed)
// ---------------------------------------------------------------------------
__device__ __align__(16) int      g_cnt_h[HH];
__device__ __align__(16) int      g_cnt_n[NN];
__device__ __align__(16) int      g_off_h[HH + 1];
__device__ __align__(16) int      g_off_n[NN + 1];
__device__ unsigned long long     g_agg_h[NBH];
__device__ unsigned long long     g_agg_n[NBN];
__device__ __align__(16) unsigned short g_rank_h[NNZ_MAX];
__device__ __align__(16) unsigned short g_rank_n[NNZ_MAX];
__device__ __align__(16) unsigned g_pack_h[NNZ_MAX];   // (row<<15)|val15, col-sorted
__device__ __align__(16) unsigned g_pack_n[NNZ_MAX];   // (col<<16)|val16, row-sorted
__device__ __align__(16) uint4    g_embs_h[NN * 16];   // embs fp16 [N,128] (25.6MB)
__device__ __align__(16) uint4    g_hyper_h[HH * 16];  // hyper fp16 [H,128] (12.8MB)

// ---------------------------------------------------------------------------
// Chain A head: zero h-side counters + lookback slots
// ---------------------------------------------------------------------------
__global__ void zero_h_kernel() {
    int i = blockIdx.x * blockDim.x + threadIdx.x;
    if (i < HH) g_cnt_h[i] = 0;
    if (i < NBH) g_agg_h[i] = 0ULL;
}

// ---------------------------------------------------------------------------
// Chain B head: zero n-side counters/slots + convert embs fp32 -> fp16
// ---------------------------------------------------------------------------
__global__ void prep_kernel(const float4* __restrict__ embs4) {
    int i = blockIdx.x * blockDim.x + threadIdx.x;
    int stride = gridDim.x * blockDim.x;
    const int TOT = NN * D4;  // 3.2M float4
    uint2* embs_h2 = reinterpret_cast<uint2*>(g_embs_h);
    for (; i < TOT; i += stride) {
        float4 v = embs4[i];
        __half2 a = __floats2half2_rn(v.x, v.y);
        __half2 b = __floats2half2_rn(v.z, v.w);
        uint2 o;
        o.x = *reinterpret_cast<unsigned int*>(&a);
        o.y = *reinterpret_cast<unsigned int*>(&b);
        embs_h2[i] = o;
        if (i < NN) g_cnt_n[i] = 0;
        if (i < NBN) g_agg_n[i] = 0ULL;
    }
}

// ---------------------------------------------------------------------------
// Histograms: 4 edges/thread (int4 load, rank quad packed into uint2)
// ---------------------------------------------------------------------------
__global__ void hist_h_kernel(const int* __restrict__ cols, int nnz) {
    int i = (blockIdx.x * blockDim.x + threadIdx.x) * 4;
    if (i + 3 < nnz) {
        int4 c = *reinterpret_cast<const int4*>(cols + i);
        unsigned r0 = (unsigned)atomicAdd(&g_cnt_h[c.x], 1);
        unsigned r1 = (unsigned)atomicAdd(&g_cnt_h[c.y], 1);
        unsigned r2 = (unsigned)atomicAdd(&g_cnt_h[c.z], 1);
        unsigned r3 = (unsigned)atomicAdd(&g_cnt_h[c.w], 1);
        *reinterpret_cast<uint2*>(g_rank_h + i) =
            make_uint2(r0 | (r1 << 16), r2 | (r3 << 16));
    } else {
        for (; i < nnz; i++)
            g_rank_h[i] = (unsigned short)atomicAdd(&g_cnt_h[cols[i]], 1);
    }
}

__global__ void hist_n_kernel(const int* __restrict__ rows, int nnz) {
    int i = (blockIdx.x * blockDim.x + threadIdx.x) * 4;
    if (i + 3 < nnz) {
        int4 r = *reinterpret_cast<const int4*>(rows + i);
        unsigned r0 = (unsigned)atomicAdd(&g_cnt_n[r.x], 1);
        unsigned r1 = (unsigned)atomicAdd(&g_cnt_n[r.y], 1);
        unsigned r2 = (unsigned)atomicAdd(&g_cnt_n[r.z], 1);
        unsigned r3 = (unsigned)atomicAdd(&g_cnt_n[r.w], 1);
        *reinterpret_cast<uint2*>(g_rank_n + i) =
            make_uint2(r0 | (r1 << 16), r2 | (r3 << 16));
    } else {
        for (; i < nnz; i++)
            g_rank_n[i] = (unsigned short)atomicAdd(&g_cnt_n[rows[i]], 1);
    }
}

// ---------------------------------------------------------------------------
// Decoupled-lookback scan (all blocks resident; <=25 blocks per side)
// ---------------------------------------------------------------------------
__device__ __forceinline__ void scan_body(const int* __restrict__ in,
                                          int* __restrict__ out,
                                          unsigned long long* __restrict__ agg,
                                          int M, int nb) {
    __shared__ int wsum[32];
    __shared__ int s_boff;
    int lb = blockIdx.x;
    int t = threadIdx.x, lane = t & 31, w = t >> 5;
    int i0 = lb * TILE + t * 4;

    int x0 = 0, x1 = 0, x2 = 0, x3 = 0;
    if (i0 + 3 < M) {
        int4 v = *reinterpret_cast<const int4*>(in + i0);
        x0 = v.x; x1 = v.y; x2 = v.z; x3 = v.w;
    } else {
        if (i0     < M) x0 = in[i0];
        if (i0 + 1 < M) x1 = in[i0 + 1];
        if (i0 + 2 < M) x2 = in[i0 + 2];
        if (i0 + 3 < M) x3 = in[i0 + 3];
    }
    int tsum = x0 + x1 + x2 + x3;

    int v = tsum;
    #pragma unroll
    for (int d = 1; d < 32; d <<= 1) {
        int y = __shfl_up_sync(0xffffffffu, v, d);
        if (lane >= d) v += y;
    }
    if (lane == 31) wsum[w] = v;
    __syncthreads();
    if (w == 0) {
        int s = wsum[lane];
        #pragma unroll
        for (int d = 1; d < 32; d <<= 1) {
            int y = __shfl_up_sync(0xffffffffu, s, d);
            if (lane >= d) s += y;
        }
        wsum[lane] = s;
    }
    __syncthreads();
    int block_total = wsum[31];

    if (t == 0) {
        unsigned long long packed = (1ULL << 63) | (unsigned long long)(unsigned)block_total;
        atomicExch(&agg[lb], packed);
    }
    if (w == 0) {
        int psum = 0;
        if (lane < lb) {
            unsigned long long pv;
            do { pv = atomicAdd(&agg[lane], 0ULL); } while (!(pv >> 63));
            psum = (int)(unsigned)pv;
        }
        #pragma unroll
        for (int d = 16; d; d >>= 1) psum += __shfl_down_sync(0xffffffffu, psum, d);
        if (lane == 0) s_boff = psum;
    }
    __syncthreads();
    int boff = s_boff;

    int woff = (w > 0) ? wsum[w - 1] : 0;
    int excl = boff + woff + v - tsum;
    int o0 = excl, o1 = o0 + x0, o2 = o1 + x1, o3 = o2 + x2;
    if (i0 + 3 < M) {
        *reinterpret_cast<int4*>(out + i0) = make_int4(o0, o1, o2, o3);
    } else {
        if (i0     < M) out[i0]     = o0;
        if (i0 + 1 < M) out[i0 + 1] = o1;
        if (i0 + 2 < M) out[i0 + 2] = o2;
    }
    if (t == 0 && lb == nb - 1) out[M] = boff + block_total;
}

__global__ void __launch_bounds__(1024, 1) scan_h_kernel() {
    scan_body(g_cnt_h, g_off_h, g_agg_h, HH, NBH);
}
__global__ void __launch_bounds__(1024, 1) scan_n_kernel() {
    scan_body(g_cnt_n, g_off_n, g_agg_n, NN, NBN);
}

// ---------------------------------------------------------------------------
// Atomic-free scatters: 4 edges/thread, vectorized meta loads.
// ---------------------------------------------------------------------------
__device__ __forceinline__ unsigned q15(float v) {
    unsigned u = __float2uint_rn(v * 32768.f);
    return u > 32767u ? 32767u : u;
}
__device__ __forceinline__ unsigned q16(float v) {
    unsigned u = __float2uint_rn(v * 65536.f);
    return u > 65535u ? 65535u : u;
}

__global__ void scatter_h_kernel(const float* __restrict__ vals,
                                 const int* __restrict__ rows,
                                 const int* __restrict__ cols, int nnz) {
    int i = (blockIdx.x * blockDim.x + threadIdx.x) * 4;
    if (i + 3 < nnz) {
        float4 v = *reinterpret_cast<const float4*>(vals + i);
        int4 r = *reinterpret_cast<const int4*>(rows + i);
        int4 c = *reinterpret_cast<const int4*>(cols + i);
        uint2 rk = *reinterpret_cast<const uint2*>(g_rank_h + i);
        int p0 = __ldg(&g_off_h[c.x]) + (int)(rk.x & 0xffffu);
        int p1 = __ldg(&g_off_h[c.y]) + (int)(rk.x >> 16);
        int p2 = __ldg(&g_off_h[c.z]) + (int)(rk.y & 0xffffu);
        int p3 = __ldg(&g_off_h[c.w]) + (int)(rk.y >> 16);
        __stcs(&g_pack_h[p0], ((unsigned)r.x << 15) | q15(v.x));
        __stcs(&g_pack_h[p1], ((unsigned)r.y << 15) | q15(v.y));
        __stcs(&g_pack_h[p2], ((unsigned)r.z << 15) | q15(v.z));
        __stcs(&g_pack_h[p3], ((unsigned)r.w << 15) | q15(v.w));
    } else {
        for (; i < nnz; i++) {
            int p = __ldg(&g_off_h[cols[i]]) + (int)g_rank_h[i];
            __stcs(&g_pack_h[p], ((unsigned)rows[i] << 15) | q15(vals[i]));
        }
    }
}

__global__ void scatter_n_kernel(const float* __restrict__ vals,
                                 const int* __restrict__ rows,
                                 const int* __restrict__ cols, int nnz) {
    int i = (blockIdx.x * blockDim.x + threadIdx.x) * 4;
    if (i + 3 < nnz) {
        float4 v = *reinterpret_cast<const float4*>(vals + i);
        int4 r = *reinterpret_cast<const int4*>(rows + i);
        int4 c = *reinterpret_cast<const int4*>(cols + i);
        uint2 rk = *reinterpret_cast<const uint2*>(g_rank_n + i);
        int q0 = __ldg(&g_off_n[r.x]) + (int)(rk.x & 0xffffu);
        int q1 = __ldg(&g_off_n[r.y]) + (int)(rk.x >> 16);
        int q2 = __ldg(&g_off_n[r.z]) + (int)(rk.y & 0xffffu);
        int q3 = __ldg(&g_off_n[r.w]) + (int)(rk.y >> 16);
        __stcs(&g_pack_n[q0], ((unsigned)c.x << 16) | q16(v.x));
        __stcs(&g_pack_n[q1], ((unsigned)c.y << 16) | q16(v.y));
        __stcs(&g_pack_n[q2], ((unsigned)c.z << 16) | q16(v.z));
        __stcs(&g_pack_n[q3], ((unsigned)c.w << 16) | q16(v.w));
    } else {
        for (; i < nnz; i++) {
            int q = __ldg(&g_off_n[rows[i]]) + (int)g_rank_n[i];
            __stcs(&g_pack_n[q], ((unsigned)cols[i] << 16) | q16(vals[i]));
        }
    }
}

// ---------------------------------------------------------------------------
// Half-warp segment reduce: a fp16 row is 256B = 16 lanes x uint4 (LDG.128).
// Lanes 0-15 process edge 2k, lanes 16-31 edge 2k+1 -> one LDG.128 warp-op
// fetches TWO edge rows. Phantom edges are safe: padded pairs are 0 -> vv=0.
// Cross-half merge via shfl_xor(16) at the end.
// ---------------------------------------------------------------------------
template <int SHIFT>
__device__ __forceinline__ void segment_reduce_hw(const int* __restrict__ off,
                                                  const unsigned* __restrict__ pairs,
                                                  const uint4* __restrict__ src,
                                                  int seg, int lane, float acc[8]) {
    const unsigned MASK = (1u << SHIFT) - 1u;
    const float SCALE = 1.0f / (float)(1u << SHIFT);
    int s = off[seg];
    int e = off[seg + 1];
    int half = lane >> 4;      // 0 or 1
    int sub  = lane & 15;
    #pragma unroll
    for (int j = 0; j < 8; j++) acc[j] = 0.f;

    int idx = s + lane;
    unsigned pr = (idx < e) ? __ldcs(&pairs[idx]) : 0u;

    for (int base = s; base < e; base += 32) {
        unsigned mine = pr;
        int nidx = base + 32 + lane;                   // prefetch next chunk
        pr = (nidx < e) ? __ldcs(&pairs[nidx]) : 0u;

        int cnt = e - base;
        if (cnt > 32) cnt = 32;
        int iters = (cnt + 1) >> 1;
        #pragma unroll 4
        for (int k = 0; k < iters; k++) {
            unsigned pk = __shfl_sync(0xffffffffu, mine, 2 * k + half);
            int   rr = (int)(pk >> SHIFT);
            float vv = (float)(pk & MASK) * SCALE;
            uint4 em = __ldg(&src[rr * 16 + sub]);
            __half2 h0 = *reinterpret_cast<__half2*>(&em.x);
            __half2 h1 = *reinterpret_cast<__half2*>(&em.y);
            __half2 h2 = *reinterpret_cast<__half2*>(&em.z);
            __half2 h3 = *reinterpret_cast<__half2*>(&em.w);
            float2 f0 = __half22float2(h0);
            float2 f1 = __half22float2(h1);
            float2 f2 = __half22float2(h2);
            float2 f3 = __half22float2(h3);
            acc[0] = fmaf(vv, f0.x, acc[0]);
            acc[1] = fmaf(vv, f0.y, acc[1]);
            acc[2] = fmaf(vv, f1.x, acc[2]);
            acc[3] = fmaf(vv, f1.y, acc[3]);
            acc[4] = fmaf(vv, f2.x, acc[4]);
            acc[5] = fmaf(vv, f2.y, acc[5]);
            acc[6] = fmaf(vv, f3.x, acc[6]);
            acc[7] = fmaf(vv, f3.y, acc[7]);
        }
    }
    #pragma unroll
    for (int j = 0; j < 8; j++)
        acc[j] += __shfl_xor_sync(0xffffffffu, acc[j], 16);
}

// spmm1: hyper = A^T @ embs  (one warp per hyperedge, fp16 out via lanes 0-15)
__global__ void __launch_bounds__(256) spmm1_kernel() {
    int gw = (blockIdx.x * blockDim.x + threadIdx.x) >> 5;
    if (gw >= HH) return;
    int lane = threadIdx.x & 31;
    float acc[8];
    segment_reduce_hw<15>(g_off_h, g_pack_h, g_embs_h, gw, lane, acc);
    if (lane < 16) {
        __half2 a = __floats2half2_rn(acc[0], acc[1]);
        __half2 b = __floats2half2_rn(acc[2], acc[3]);
        __half2 c = __floats2half2_rn(acc[4], acc[5]);
        __half2 d = __floats2half2_rn(acc[6], acc[7]);
        uint4 o;
        o.x = *reinterpret_cast<unsigned int*>(&a);
        o.y = *reinterpret_cast<unsigned int*>(&b);
        o.z = *reinterpret_cast<unsigned int*>(&c);
        o.w = *reinterpret_cast<unsigned int*>(&d);
        g_hyper_h[gw * 16 + lane] = o;
    }
}

// spmm2: out = LeakyReLU(A @ hyper)  (one warp per node, fp32 out via lanes 0-15)
__global__ void __launch_bounds__(256) spmm2_kernel(float4* __restrict__ out4) {
    int gw = (blockIdx.x * blockDim.x + threadIdx.x) >> 5;
    if (gw >= NN) return;
    int lane = threadIdx.x & 31;
    float acc[8];
    segment_reduce_hw<16>(g_off_n, g_pack_n, g_hyper_h, gw, lane, acc);
    if (lane < 16) {
        #pragma unroll
        for (int j = 0; j < 8; j++)
            acc[j] = acc[j] >= 0.f ? acc[j] : LEAKY_SLOPE * acc[j];
        int base = gw * D4 + lane * 2;   // float4 index: 2 per lane
        __stcs(&out4[base],     make_float4(acc[0], acc[1], acc[2], acc[3]));
        __stcs(&out4[base + 1], make_float4(acc[4], acc[5], acc[6], acc[7]));
    }
}

// ---------------------------------------------------------------------------
// Launch: fork-join dual chains (n-side sort hides under h-side sort + spmm1)
// ---------------------------------------------------------------------------
extern "C" void kernel_launch(void* const* d_in, const int* in_sizes, int n_in,
                              void* d_out, int out_size) {
    const float* vals = (const float*)d_in[0];
    const float* embs = (const float*)d_in[1];
    const int*   rows = (const int*)d_in[2];
    const int*   cols = (const int*)d_in[3];
    int nnz = in_sizes[0];
    if (nnz > NNZ_MAX) nnz = NNZ_MAX;

    float4* out4 = (float4*)d_out;
    const float4* embs4 = (const float4*)embs;

    const int B = 256;
    int quad_blocks = ((nnz + 3) / 4 + B - 1) / B;

    cudaStream_t s1;
    cudaStreamCreateWithFlags(&s1, cudaStreamNonBlocking);
    cudaEvent_t evFork, evPrep, evScatN;
    cudaEventCreateWithFlags(&evFork,  cudaEventDisableTiming);
    cudaEventCreateWithFlags(&evPrep,  cudaEventDisableTiming);
    cudaEventCreateWithFlags(&evScatN, cudaEventDisableTiming);

    // fork
    cudaEventRecord(evFork, 0);
    cudaStreamWaitEvent(s1, evFork, 0);

    // chain B (stream s1): prep -> hist_n -> scan_n -> scatter_n
    prep_kernel<<<(NN * D4 + B - 1) / B, B, 0, s1>>>(embs4);
    cudaEventRecord(evPrep, s1);
    hist_n_kernel<<<quad_blocks, B, 0, s1>>>(rows, nnz);
    scan_n_kernel<<<NBN, 1024, 0, s1>>>();
    scatter_n_kernel<<<quad_blocks, B, 0, s1>>>(vals, rows, cols, nnz);
    cudaEventRecord(evScatN, s1);

    // chain A (origin stream): zero_h -> hist_h -> scan_h -> scatter_h
    zero_h_kernel<<<(HH + B - 1) / B, B>>>();
    hist_h_kernel<<<quad_blocks, B>>>(cols, nnz);
    scan_h_kernel<<<NBH, 1024>>>();
    scatter_h_kernel<<<quad_blocks, B>>>(vals, rows, cols, nnz);

    // spmm1 needs embs_h (chain B's prep) + chain A's pack_h
    cudaStreamWaitEvent(0, evPrep, 0);
    spmm1_kernel<<<(HH * 32 + B - 1) / B, B>>>();

    // spmm2 needs pack_n (chain B fully joined) + hyper (spmm1)
    cudaStreamWaitEvent(0, evScatN, 0);
    spmm2_kernel<<<(NN * 32 + B - 1) / B, B>>>(out4);
}

// round 10
// speedup vs baseline: 1.1053x; 1.0037x over previous
#include <cuda_runtime.h>
#include <cuda_fp16.h>
#include <cuda_bf16.h>

// Problem constants (fixed by the reference)
#define NNZ_MAX 3200000
#define NN      100000   // nodes  (< 2^17)
#define HH      50000    // hyperedges (< 2^16)
#define D4      32       // 128 floats per row
#define LEAKY_SLOPE 0.5f

#define TILE    4096                       // scan tile (1024 thr x 4)
#define NBH     ((HH + TILE - 1) / TILE)   // 13
#define NBN     ((NN + TILE - 1) / TILE)   // 25

// ---------------------------------------------------------------------------
// Static device scratch (no runtime allocation allowed)
// ---------------------------------------------------------------------------
__device__ __align__(16) int      g_cnt_h[HH];
__device__ __align__(16) int      g_cnt_n[NN];
__device__ __align__(16) int      g_off_h[HH + 1];
__device__ __align__(16) int      g_off_n[NN + 1];
__device__ unsigned long long     g_agg_h[NBH];
__device__ unsigned long long     g_agg_n[NBN];
__device__ __align__(16) unsigned short g_rank_h[NNZ_MAX];
__device__ __align__(16) unsigned short g_rank_n[NNZ_MAX];
__device__ __align__(16) unsigned g_pack_h[NNZ_MAX];   // (row<<15)|val15, col-sorted
__device__ __align__(16) unsigned g_pack_n[NNZ_MAX];   // (col<<16)|val16, row-sorted
__device__ __align__(16) uint4    g_embs_h[NN * 16];   // embs fp16 [N,128] (25.6MB)
__device__ __align__(16) uint4    g_hyper_h[HH * 16];  // hyper fp16 [H,128] (12.8MB)

// ---------------------------------------------------------------------------
// Chain A head: zero h-side counters + lookback slots
// ---------------------------------------------------------------------------
__global__ void zero_h_kernel() {
    int i = blockIdx.x * blockDim.x + threadIdx.x;
    if (i < HH) g_cnt_h[i] = 0;
    if (i < NBH) g_agg_h[i] = 0ULL;
}

// ---------------------------------------------------------------------------
// Chain B head: zero n-side counters/slots + convert embs fp32 -> fp16
// ---------------------------------------------------------------------------
__global__ void prep_kernel(const float4* __restrict__ embs4) {
    int i = blockIdx.x * blockDim.x + threadIdx.x;
    int stride = gridDim.x * blockDim.x;
    const int TOT = NN * D4;  // 3.2M float4
    uint2* embs_h2 = reinterpret_cast<uint2*>(g_embs_h);
    for (; i < TOT; i += stride) {
        float4 v = embs4[i];
        __half2 a = __floats2half2_rn(v.x, v.y);
        __half2 b = __floats2half2_rn(v.z, v.w);
        uint2 o;
        o.x = *reinterpret_cast<unsigned int*>(&a);
        o.y = *reinterpret_cast<unsigned int*>(&b);
        embs_h2[i] = o;
        if (i < NN) g_cnt_n[i] = 0;
        if (i < NBN) g_agg_n[i] = 0ULL;
    }
}

// ---------------------------------------------------------------------------
// Histograms: 4 edges/thread (int4 load, rank quad packed into uint2)
// ---------------------------------------------------------------------------
__global__ void hist_h_kernel(const int* __restrict__ cols, int nnz) {
    int i = (blockIdx.x * blockDim.x + threadIdx.x) * 4;
    if (i + 3 < nnz) {
        int4 c = *reinterpret_cast<const int4*>(cols + i);
        unsigned r0 = (unsigned)atomicAdd(&g_cnt_h[c.x], 1);
        unsigned r1 = (unsigned)atomicAdd(&g_cnt_h[c.y], 1);
        unsigned r2 = (unsigned)atomicAdd(&g_cnt_h[c.z], 1);
        unsigned r3 = (unsigned)atomicAdd(&g_cnt_h[c.w], 1);
        *reinterpret_cast<uint2*>(g_rank_h + i) =
            make_uint2(r0 | (r1 << 16), r2 | (r3 << 16));
    } else {
        for (; i < nnz; i++)
            g_rank_h[i] = (unsigned short)atomicAdd(&g_cnt_h[cols[i]], 1);
    }
}

__global__ void hist_n_kernel(const int* __restrict__ rows, int nnz) {
    int i = (blockIdx.x * blockDim.x + threadIdx.x) * 4;
    if (i + 3 < nnz) {
        int4 r = *reinterpret_cast<const int4*>(rows + i);
        unsigned r0 = (unsigned)atomicAdd(&g_cnt_n[r.x], 1);
        unsigned r1 = (unsigned)atomicAdd(&g_cnt_n[r.y], 1);
        unsigned r2 = (unsigned)atomicAdd(&g_cnt_n[r.z], 1);
        unsigned r3 = (unsigned)atomicAdd(&g_cnt_n[r.w], 1);
        *reinterpret_cast<uint2*>(g_rank_n + i) =
            make_uint2(r0 | (r1 << 16), r2 | (r3 << 16));
    } else {
        for (; i < nnz; i++)
            g_rank_n[i] = (unsigned short)atomicAdd(&g_cnt_n[rows[i]], 1);
    }
}

// ---------------------------------------------------------------------------
// Decoupled-lookback scan (all blocks resident; <=25 blocks per side)
// ---------------------------------------------------------------------------
__device__ __forceinline__ void scan_body(const int* __restrict__ in,
                                          int* __restrict__ out,
                                          unsigned long long* __restrict__ agg,
                                          int M, int nb) {
    __shared__ int wsum[32];
    __shared__ int s_boff;
    int lb = blockIdx.x;
    int t = threadIdx.x, lane = t & 31, w = t >> 5;
    int i0 = lb * TILE + t * 4;

    int x0 = 0, x1 = 0, x2 = 0, x3 = 0;
    if (i0 + 3 < M) {
        int4 v = *reinterpret_cast<const int4*>(in + i0);
        x0 = v.x; x1 = v.y; x2 = v.z; x3 = v.w;
    } else {
        if (i0     < M) x0 = in[i0];
        if (i0 + 1 < M) x1 = in[i0 + 1];
        if (i0 + 2 < M) x2 = in[i0 + 2];
        if (i0 + 3 < M) x3 = in[i0 + 3];
    }
    int tsum = x0 + x1 + x2 + x3;

    int v = tsum;
    #pragma unroll
    for (int d = 1; d < 32; d <<= 1) {
        int y = __shfl_up_sync(0xffffffffu, v, d);
        if (lane >= d) v += y;
    }
    if (lane == 31) wsum[w] = v;
    __syncthreads();
    if (w == 0) {
        int s = wsum[lane];
        #pragma unroll
        for (int d = 1; d < 32; d <<= 1) {
            int y = __shfl_up_sync(0xffffffffu, s, d);
            if (lane >= d) s += y;
        }
        wsum[lane] = s;
    }
    __syncthreads();
    int block_total = wsum[31];

    if (t == 0) {
        unsigned long long packed = (1ULL << 63) | (unsigned long long)(unsigned)block_total;
        atomicExch(&agg[lb], packed);
    }
    if (w == 0) {
        int psum = 0;
        if (lane < lb) {
            unsigned long long pv;
            do { pv = atomicAdd(&agg[lane], 0ULL); } while (!(pv >> 63));
            psum = (int)(unsigned)pv;
        }
        #pragma unroll
        for (int d = 16; d; d >>= 1) psum += __shfl_down_sync(0xffffffffu, psum, d);
        if (lane == 0) s_boff = psum;
    }
    __syncthreads();
    int boff = s_boff;

    int woff = (w > 0) ? wsum[w - 1] : 0;
    int excl = boff + woff + v - tsum;
    int o0 = excl, o1 = o0 + x0, o2 = o1 + x1, o3 = o2 + x2;
    if (i0 + 3 < M) {
        *reinterpret_cast<int4*>(out + i0) = make_int4(o0, o1, o2, o3);
    } else {
        if (i0     < M) out[i0]     = o0;
        if (i0 + 1 < M) out[i0 + 1] = o1;
        if (i0 + 2 < M) out[i0 + 2] = o2;
    }
    if (t == 0 && lb == nb - 1) out[M] = boff + block_total;
}

__global__ void __launch_bounds__(1024, 1) scan_h_kernel() {
    scan_body(g_cnt_h, g_off_h, g_agg_h, HH, NBH);
}
__global__ void __launch_bounds__(1024, 1) scan_n_kernel() {
    scan_body(g_cnt_n, g_off_n, g_agg_n, NN, NBN);
}

// ---------------------------------------------------------------------------
// Atomic-free scatters: 4 edges/thread, vectorized meta loads.
// ---------------------------------------------------------------------------
__device__ __forceinline__ unsigned q15(float v) {
    unsigned u = __float2uint_rn(v * 32768.f);
    return u > 32767u ? 32767u : u;
}
__device__ __forceinline__ unsigned q16(float v) {
    unsigned u = __float2uint_rn(v * 65536.f);
    return u > 65535u ? 65535u : u;
}

__global__ void scatter_h_kernel(const float* __restrict__ vals,
                                 const int* __restrict__ rows,
                                 const int* __restrict__ cols, int nnz) {
    int i = (blockIdx.x * blockDim.x + threadIdx.x) * 4;
    if (i + 3 < nnz) {
        float4 v = *reinterpret_cast<const float4*>(vals + i);
        int4 r = *reinterpret_cast<const int4*>(rows + i);
        int4 c = *reinterpret_cast<const int4*>(cols + i);
        uint2 rk = *reinterpret_cast<const uint2*>(g_rank_h + i);
        int p0 = __ldg(&g_off_h[c.x]) + (int)(rk.x & 0xffffu);
        int p1 = __ldg(&g_off_h[c.y]) + (int)(rk.x >> 16);
        int p2 = __ldg(&g_off_h[c.z]) + (int)(rk.y & 0xffffu);
        int p3 = __ldg(&g_off_h[c.w]) + (int)(rk.y >> 16);
        __stcs(&g_pack_h[p0], ((unsigned)r.x << 15) | q15(v.x));
        __stcs(&g_pack_h[p1], ((unsigned)r.y << 15) | q15(v.y));
        __stcs(&g_pack_h[p2], ((unsigned)r.z << 15) | q15(v.z));
        __stcs(&g_pack_h[p3], ((unsigned)r.w << 15) | q15(v.w));
    } else {
        for (; i < nnz; i++) {
            int p = __ldg(&g_off_h[cols[i]]) + (int)g_rank_h[i];
            __stcs(&g_pack_h[p], ((unsigned)rows[i] << 15) | q15(vals[i]));
        }
    }
}

__global__ void scatter_n_kernel(const float* __restrict__ vals,
                                 const int* __restrict__ rows,
                                 const int* __restrict__ cols, int nnz) {
    int i = (blockIdx.x * blockDim.x + threadIdx.x) * 4;
    if (i + 3 < nnz) {
        float4 v = *reinterpret_cast<const float4*>(vals + i);
        int4 r = *reinterpret_cast<const int4*>(rows + i);
        int4 c = *reinterpret_cast<const int4*>(cols + i);
        uint2 rk = *reinterpret_cast<const uint2*>(g_rank_n + i);
        int q0 = __ldg(&g_off_n[r.x]) + (int)(rk.x & 0xffffu);
        int q1 = __ldg(&g_off_n[r.y]) + (int)(rk.x >> 16);
        int q2 = __ldg(&g_off_n[r.z]) + (int)(rk.y & 0xffffu);
        int q3 = __ldg(&g_off_n[r.w]) + (int)(rk.y >> 16);
        __stcs(&g_pack_n[q0], ((unsigned)c.x << 16) | q16(v.x));
        __stcs(&g_pack_n[q1], ((unsigned)c.y << 16) | q16(v.y));
        __stcs(&g_pack_n[q2], ((unsigned)c.z << 16) | q16(v.z));
        __stcs(&g_pack_n[q3], ((unsigned)c.w << 16) | q16(v.w));
    } else {
        for (; i < nnz; i++) {
            int q = __ldg(&g_off_n[rows[i]]) + (int)g_rank_n[i];
            __stcs(&g_pack_n[q], ((unsigned)cols[i] << 16) | q16(vals[i]));
        }
    }
}

// ---------------------------------------------------------------------------
// Half-warp segment reduce: a fp16 row is 256B = 16 lanes x uint4 (LDG.128).
// Lanes 0-15 process edge 2k, lanes 16-31 edge 2k+1 -> one LDG.128 warp-op
// fetches TWO edge rows. Phantom edges are safe: padded pairs are 0 -> vv=0.
// Cross-half merge via shfl_xor(16) at the end.
// ---------------------------------------------------------------------------
template <int SHIFT>
__device__ __forceinline__ void segment_reduce_hw(const int* __restrict__ off,
                                                  const unsigned* __restrict__ pairs,
                                                  const uint4* __restrict__ src,
                                                  int seg, int lane, float acc[8]) {
    const unsigned MASK = (1u << SHIFT) - 1u;
    const float SCALE = 1.0f / (float)(1u << SHIFT);
    int s = off[seg];
    int e = off[seg + 1];
    int half = lane >> 4;      // 0 or 1
    int sub  = lane & 15;
    #pragma unroll
    for (int j = 0; j < 8; j++) acc[j] = 0.f;

    int idx = s + lane;
    unsigned pr = (idx < e) ? __ldcs(&pairs[idx]) : 0u;

    for (int base = s; base < e; base += 32) {
        unsigned mine = pr;
        int nidx = base + 32 + lane;                   // prefetch next chunk
        pr = (nidx < e) ? __ldcs(&pairs[nidx]) : 0u;

        int cnt = e - base;
        if (cnt > 32) cnt = 32;
        int iters = (cnt + 1) >> 1;
        #pragma unroll 4
        for (int k = 0; k < iters; k++) {
            unsigned pk = __shfl_sync(0xffffffffu, mine, 2 * k + half);
            int   rr = (int)(pk >> SHIFT);
            float vv = (float)(pk & MASK) * SCALE;
            uint4 em = __ldg(&src[rr * 16 + sub]);
            __half2 h0 = *reinterpret_cast<__half2*>(&em.x);
            __half2 h1 = *reinterpret_cast<__half2*>(&em.y);
            __half2 h2 = *reinterpret_cast<__half2*>(&em.z);
            __half2 h3 = *reinterpret_cast<__half2*>(&em.w);
            float2 f0 = __half22float2(h0);
            float2 f1 = __half22float2(h1);
            float2 f2 = __half22float2(h2);
            float2 f3 = __half22float2(h3);
            acc[0] = fmaf(vv, f0.x, acc[0]);
            acc[1] = fmaf(vv, f0.y, acc[1]);
            acc[2] = fmaf(vv, f1.x, acc[2]);
            acc[3] = fmaf(vv, f1.y, acc[3]);
            acc[4] = fmaf(vv, f2.x, acc[4]);
            acc[5] = fmaf(vv, f2.y, acc[5]);
            acc[6] = fmaf(vv, f3.x, acc[6]);
            acc[7] = fmaf(vv, f3.y, acc[7]);
        }
    }
    #pragma unroll
    for (int j = 0; j < 8; j++)
        acc[j] += __shfl_xor_sync(0xffffffffu, acc[j], 16);
}

// spmm1: hyper = A^T @ embs  (one warp per hyperedge, fp16 out via lanes 0-15)
__global__ void __launch_bounds__(256) spmm1_kernel() {
    int gw = (blockIdx.x * blockDim.x + threadIdx.x) >> 5;
    if (gw >= HH) return;
    int lane = threadIdx.x & 31;
    float acc[8];
    segment_reduce_hw<15>(g_off_h, g_pack_h, g_embs_h, gw, lane, acc);
    if (lane < 16) {
        __half2 a = __floats2half2_rn(acc[0], acc[1]);
        __half2 b = __floats2half2_rn(acc[2], acc[3]);
        __half2 c = __floats2half2_rn(acc[4], acc[5]);
        __half2 d = __floats2half2_rn(acc[6], acc[7]);
        uint4 o;
        o.x = *reinterpret_cast<unsigned int*>(&a);
        o.y = *reinterpret_cast<unsigned int*>(&b);
        o.z = *reinterpret_cast<unsigned int*>(&c);
        o.w = *reinterpret_cast<unsigned int*>(&d);
        g_hyper_h[gw * 16 + lane] = o;
    }
}

// spmm2: out = LeakyReLU(A @ hyper)  (one warp per node, fp32 out via lanes 0-15)
__global__ void __launch_bounds__(256) spmm2_kernel(float4* __restrict__ out4) {
    int gw = (blockIdx.x * blockDim.x + threadIdx.x) >> 5;
    if (gw >= NN) return;
    int lane = threadIdx.x & 31;
    float acc[8];
    segment_reduce_hw<16>(g_off_n, g_pack_n, g_hyper_h, gw, lane, acc);
    if (lane < 16) {
        #pragma unroll
        for (int j = 0; j < 8; j++)
            acc[j] = acc[j] >= 0.f ? acc[j] : LEAKY_SLOPE * acc[j];
        int base = gw * D4 + lane * 2;   // float4 index: 2 per lane
        __stcs(&out4[base],     make_float4(acc[0], acc[1], acc[2], acc[3]));
        __stcs(&out4[base + 1], make_float4(acc[4], acc[5], acc[6], acc[7]));
    }
}

// ---------------------------------------------------------------------------
// Launch: fork-join dual chains (n-side sort hides under h-side sort + spmm1)
// ---------------------------------------------------------------------------
extern "C" void kernel_launch(void* const* d_in, const int* in_sizes, int n_in,
                              void* d_out, int out_size) {
    const float* vals = (const float*)d_in[0];
    const float* embs = (const float*)d_in[1];
    const int*   rows = (const int*)d_in[2];
    const int*   cols = (const int*)d_in[3];
    int nnz = in_sizes[0];
    if (nnz > NNZ_MAX) nnz = NNZ_MAX;

    float4* out4 = (float4*)d_out;
    const float4* embs4 = (const float4*)embs;

    const int B = 256;
    int quad_blocks = ((nnz + 3) / 4 + B - 1) / B;

    cudaStream_t s1;
    cudaStreamCreateWithFlags(&s1, cudaStreamNonBlocking);
    cudaEvent_t evFork, evPrep, evScatN;
    cudaEventCreateWithFlags(&evFork,  cudaEventDisableTiming);
    cudaEventCreateWithFlags(&evPrep,  cudaEventDisableTiming);
    cudaEventCreateWithFlags(&evScatN, cudaEventDisableTiming);

    // fork
    cudaEventRecord(evFork, 0);
    cudaStreamWaitEvent(s1, evFork, 0);

    // chain B (stream s1): prep -> hist_n -> scan_n -> scatter_n
    prep_kernel<<<(NN * D4 + B - 1) / B, B, 0, s1>>>(embs4);
    cudaEventRecord(evPrep, s1);
    hist_n_kernel<<<quad_blocks, B, 0, s1>>>(rows, nnz);
    scan_n_kernel<<<NBN, 1024, 0, s1>>>();
    scatter_n_kernel<<<quad_blocks, B, 0, s1>>>(vals, rows, cols, nnz);
    cudaEventRecord(evScatN, s1);

    // chain A (origin stream): zero_h -> hist_h -> scan_h -> scatter_h
    zero_h_kernel<<<(HH + B - 1) / B, B>>>();
    hist_h_kernel<<<quad_blocks, B>>>(cols, nnz);
    scan_h_kernel<<<NBH, 1024>>>();
    scatter_h_kernel<<<quad_blocks, B>>>(vals, rows, cols, nnz);

    // spmm1 needs embs_h (chain B's prep) + chain A's pack_h
    cudaStreamWaitEvent(0, evPrep, 0);
    spmm1_kernel<<<(HH * 32 + B - 1) / B, B>>>();

    // spmm2 needs pack_n (chain B fully joined) + hyper (spmm1)
    cudaStreamWaitEvent(0, evScatN, 0);
    spmm2_kernel<<<(NN * 32 + B - 1) / B, B>>>(out4);
}